// round 15
// baseline (speedup 1.0000x reference)
#include <cuda_runtime.h>
#include <cuda_fp16.h>
#include <cstdint>
#include <math.h>

// ---------------------------------------------------------------------------
// IDMRF loss. Small stages fused across layers; GEMM templated per layer
// (compile-time C,P -> 2 CTA/SM) with register fragment double-buffering.
// (R12 configuration — measured 277 us — with colsum L3 using 16B loads.)
//   Layer3: B=4, C=256, P=4096, w=1.  Layer4: B=4, C=512, P=1024, w=2.
// ---------------------------------------------------------------------------

#define P3 4096
#define C3 256
#define P4 1024
#define C4 512

#define S4_OFF  ((size_t)4 * P3 * P3)
#define T4_OFF  ((size_t)4 * C3 * P3)
#define V4_OFF  16384
#define NVEC    20480
#define PP4_OFF 524288

__device__ __half   g_S[S4_OFF + (size_t)4 * P4 * P4];
__device__ __half   g_tn[T4_OFF + (size_t)4 * C4 * P4];
__device__ __half   g_gn[T4_OFF + (size_t)4 * C4 * P4];
__device__ unsigned g_colmax[NVEC];
__device__ float    g_Z[NVEC];
__device__ float    g_s1[NVEC];
__device__ float    g_aux[NVEC];
__device__ float    g_lsum[8];
__device__ float    g_pst[PP4_OFF + 64 * 4096], g_pstt[PP4_OFF + 64 * 4096];
__device__ float    g_psg[PP4_OFF + 64 * 4096], g_psgg[PP4_OFF + 64 * 4096];
__device__ float    g_mean[NVEC], g_nt[NVEC], g_ng[NVEC];

__device__ __forceinline__ unsigned fenc(float f) {
    unsigned u = __float_as_uint(f);
    return (u & 0x80000000u) ? ~u : (u | 0x80000000u);
}
__device__ __forceinline__ float fdec(unsigned u) {
    return __uint_as_float((u & 0x80000000u) ? (u ^ 0x80000000u) : ~u);
}

__device__ __forceinline__ float fast_exp(float x) {
    float y = fmaxf(x * 1.4426950408889634f, -126.0f);
    float n = rintf(y);
    float f = y - n;
    float p = 1.3333558e-3f;
    p = fmaf(p, f, 9.6181291e-3f);
    p = fmaf(p, f, 5.5504109e-2f);
    p = fmaf(p, f, 2.4022651e-1f);
    p = fmaf(p, f, 6.9314718e-1f);
    p = fmaf(p, f, 1.0f);
    return p * __uint_as_float(((unsigned)((int)n + 127)) << 23);
}

__device__ __forceinline__ void ldsm4t(uint32_t& r0, uint32_t& r1,
                                       uint32_t& r2, uint32_t& r3, unsigned addr) {
    asm volatile("ldmatrix.sync.aligned.m8n8.x4.trans.shared.b16 {%0,%1,%2,%3},[%4];"
                 : "=r"(r0), "=r"(r1), "=r"(r2), "=r"(r3) : "r"(addr));
}

// ---- stage 1: split-K partial stats (both layers) ---------------------------
__global__ void stats_kernel(const float* __restrict__ gen3, const float* __restrict__ tar3,
                             const float* __restrict__ gen4, const float* __restrict__ tar4) {
    int bid = blockIdx.x;
    const float *g, *t;
    int P, sp, b, x, pbase, pstride;
    if (bid < 512) {
        x = bid & 3; sp = (bid >> 2) & 31; b = bid >> 7;
        g = gen3 + (size_t)b * C3 * P3; t = tar3 + (size_t)b * C3 * P3;
        P = P3; pbase = 0; pstride = 16384;
    } else {
        int r = bid - 512;
        x = 0; sp = r & 63; b = r >> 6;
        g = gen4 + (size_t)b * C4 * P4; t = tar4 + (size_t)b * C4 * P4;
        P = P4; pbase = PP4_OFF; pstride = 4096;
    }
    int hw = x * 1024 + threadIdx.x * 4;
    g += (size_t)(sp * 8) * P + hw;
    t += (size_t)(sp * 8) * P + hw;
    float st[4] = {0,0,0,0}, stt[4] = {0,0,0,0}, sg[4] = {0,0,0,0}, sgg[4] = {0,0,0,0};
#pragma unroll
    for (int c = 0; c < 8; c++) {
        float4 tv = *(const float4*)&t[(size_t)c * P];
        float4 gv = *(const float4*)&g[(size_t)c * P];
        st[0] += tv.x; stt[0] += tv.x * tv.x; sg[0] += gv.x; sgg[0] += gv.x * gv.x;
        st[1] += tv.y; stt[1] += tv.y * tv.y; sg[1] += gv.y; sgg[1] += gv.y * gv.y;
        st[2] += tv.z; stt[2] += tv.z * tv.z; sg[2] += gv.z; sgg[2] += gv.z * gv.z;
        st[3] += tv.w; stt[3] += tv.w * tv.w; sg[3] += gv.w; sgg[3] += gv.w * gv.w;
    }
    size_t base = (size_t)pbase + (size_t)sp * pstride + (size_t)b * P + hw;
    *(float4*)&g_pst[base]  = make_float4(st[0], st[1], st[2], st[3]);
    *(float4*)&g_pstt[base] = make_float4(stt[0], stt[1], stt[2], stt[3]);
    *(float4*)&g_psg[base]  = make_float4(sg[0], sg[1], sg[2], sg[3]);
    *(float4*)&g_psgg[base] = make_float4(sgg[0], sgg[1], sgg[2], sgg[3]);
}

// ---- stage 2: reduce partials; zero colmax/Z/lsum/out -----------------------
__global__ void finalize_kernel(float* out) {
    int i = blockIdx.x * blockDim.x + threadIdx.x;
    if (i >= NVEC) return;
    int C, NS, pbase, pstride, j;
    if (i < V4_OFF) { C = C3; NS = 32; pbase = 0; pstride = 16384; j = i; }
    else            { C = C4; NS = 64; pbase = PP4_OFF; pstride = 4096; j = i - V4_OFF; }
    float st = 0.f, stt = 0.f, sg = 0.f, sgg = 0.f;
    for (int s = 0; s < NS; s++) {
        size_t o = (size_t)pbase + (size_t)s * pstride + j;
        st += g_pst[o]; stt += g_pstt[o]; sg += g_psg[o]; sgg += g_psgg[o];
    }
    float mean = st / (float)C;
    float vt = stt - (float)C * mean * mean;
    float vg = sgg - 2.f * mean * sg + (float)C * mean * mean;
    g_mean[i] = mean;
    g_nt[i] = rsqrtf(fmaxf(vt, 1e-30f));
    g_ng[i] = rsqrtf(fmaxf(vg, 1e-30f));
    g_colmax[i] = 0u;
    g_Z[i] = 0.f;
    if (i < 8) g_lsum[i] = 0.f;
    if (i == 0) out[0] = 0.f;
}

// ---- stage 3: write normalized fp16 features (both layers) ------------------
__global__ void write_kernel(const float* __restrict__ gen3, const float* __restrict__ tar3,
                             const float* __restrict__ gen4, const float* __restrict__ tar4) {
    int bid = blockIdx.x;
    const float *g, *t;
    size_t foff, toff;
    int vb, c, hw, P;
    if (bid < 4096) {
        int b = bid >> 10, blk = bid & 1023;
        int idx = blk * 256 + threadIdx.x;
        c = idx >> 10; hw = (idx & 1023) * 4; P = P3;
        foff = (size_t)b * C3 * P3; toff = foff;
        g = gen3; t = tar3; vb = b * P3;
    } else {
        int r = bid - 4096;
        int b = r >> 9, blk = r & 511;
        int idx = blk * 256 + threadIdx.x;
        c = idx >> 8; hw = (idx & 255) * 4; P = P4;
        foff = (size_t)b * C4 * P4; toff = T4_OFF + foff;
        g = gen4; t = tar4; vb = V4_OFF + b * P4;
    }
    size_t off = foff + (size_t)c * P + hw;
    size_t dst = toff + (size_t)c * P + hw;
    size_t pb = (size_t)vb + hw;
    float4 tv = *(const float4*)&t[off];
    float4 gv = *(const float4*)&g[off];
    float4 mean = *(const float4*)&g_mean[pb];
    float4 nt   = *(const float4*)&g_nt[pb];
    float4 ng   = *(const float4*)&g_ng[pb];
    __half2 t01 = __floats2half2_rn((tv.x - mean.x) * nt.x, (tv.y - mean.y) * nt.y);
    __half2 t23 = __floats2half2_rn((tv.z - mean.z) * nt.z, (tv.w - mean.w) * nt.w);
    __half2 g01 = __floats2half2_rn((gv.x - mean.x) * ng.x, (gv.y - mean.y) * ng.y);
    __half2 g23 = __floats2half2_rn((gv.z - mean.z) * ng.z, (gv.w - mean.w) * ng.w);
    uint2 tp, gp;
    tp.x = *(unsigned*)&t01; tp.y = *(unsigned*)&t23;
    gp.x = *(unsigned*)&g01; gp.y = *(unsigned*)&g23;
    *(uint2*)&g_tn[dst] = tp;
    *(uint2*)&g_gn[dst] = gp;
}

// ---- stage 4: GEMM + colmax, templated; register fragment double-buffer -----
#define LDH 136
#define ASTAGE (64 * LDH * 2)
#define NSTAGE 3
#define SLD 136

template <int C, int P, size_t TBASE, size_t SBASE, int VB>
__global__ void __launch_bounds__(256, 2)
gemm_fp16_colmax() {
    extern __shared__ float smem[];
    __shared__ unsigned cms[128];
    constexpr int NTILE = P / 128;
    int bid = blockIdx.x;
    int b = bid / (NTILE * NTILE);
    int rem = bid % (NTILE * NTILE);
    int m0 = (rem / NTILE) * 128;
    int n0 = (rem % NTILE) * 128;
    const __half* Ab = g_tn + TBASE + (size_t)b * C * P;
    const __half* Bb = g_gn + TBASE + (size_t)b * C * P;
    int tid = threadIdx.x, lane = tid & 31, wid = tid >> 5;
    int wm = (wid & 3) * 32;
    int wn = (wid >> 2) * 64;
    if (tid < 128) cms[tid] = 0u;

    unsigned sA = (unsigned)__cvta_generic_to_shared(smem);
    unsigned sB = sA + (unsigned)NSTAGE * ASTAGE;

    float acc[2][8][4];
#pragma unroll
    for (int mt = 0; mt < 2; mt++)
#pragma unroll
        for (int nt = 0; nt < 8; nt++)
#pragma unroll
            for (int j = 0; j < 4; j++) acc[mt][nt][j] = 0.f;

    constexpr int nk = C / 64;

    auto issue_stage = [&](int s, int k0) {
#pragma unroll
        for (int i = 0; i < 4; i++) {
            int idx = tid + i * 256;
            int r = idx >> 4;
            int cm = (idx & 15) * 8;
            unsigned da = sA + (unsigned)s * ASTAGE + (unsigned)((r * LDH + cm) * 2);
            const __half* pa = Ab + (size_t)(k0 + r) * P + m0 + cm;
            asm volatile("cp.async.cg.shared.global [%0], [%1], 16;" :: "r"(da), "l"(pa));
            unsigned db = sB + (unsigned)s * ASTAGE + (unsigned)((r * LDH + cm) * 2);
            const __half* pb = Bb + (size_t)(k0 + r) * P + n0 + cm;
            asm volatile("cp.async.cg.shared.global [%0], [%1], 16;" :: "r"(db), "l"(pb));
        }
    };

    issue_stage(0, 0);
    asm volatile("cp.async.commit_group;");
    issue_stage(1, 64);
    asm volatile("cp.async.commit_group;");

    int g = lane >> 3, li = lane & 7;
    int akoff = (g >> 1) << 3, amoff = (g & 1) << 3;
    int bkoff = (g & 1) << 3,  bnoff = (g >> 1) << 3;

    uint32_t afb[2][2][4];
    uint32_t bfb[2][8][2];

    auto load_frags = [&](unsigned aS, unsigned bS, int kb, int buf) {
#pragma unroll
        for (int mt = 0; mt < 2; mt++) {
            int row = kb + akoff + li;
            int col = wm + mt * 16 + amoff;
            ldsm4t(afb[buf][mt][0], afb[buf][mt][1], afb[buf][mt][2], afb[buf][mt][3],
                   aS + (unsigned)((row * LDH + col) * 2));
        }
#pragma unroll
        for (int np = 0; np < 4; np++) {
            int row = kb + bkoff + li;
            int col = wn + np * 16 + bnoff;
            uint32_t r0, r1, r2, r3;
            ldsm4t(r0, r1, r2, r3, bS + (unsigned)((row * LDH + col) * 2));
            bfb[buf][np * 2][0] = r0; bfb[buf][np * 2][1] = r1;
            bfb[buf][np * 2 + 1][0] = r2; bfb[buf][np * 2 + 1][1] = r3;
        }
    };

    int sidx = 0;
    for (int kt = 0; kt < nk; kt++) {
        asm volatile("cp.async.wait_group 1;");
        __syncthreads();
        if (kt + 2 < nk) {
            int s2 = sidx + 2; if (s2 >= NSTAGE) s2 -= NSTAGE;
            issue_stage(s2, (kt + 2) * 64);
        }
        asm volatile("cp.async.commit_group;");
        unsigned aS = sA + (unsigned)sidx * ASTAGE;
        unsigned bS = sB + (unsigned)sidx * ASTAGE;
        load_frags(aS, bS, 0, 0);
#pragma unroll
        for (int k16 = 0; k16 < 4; k16++) {
            if (k16 < 3) load_frags(aS, bS, (k16 + 1) * 16, (k16 + 1) & 1);
            int cb = k16 & 1;
#pragma unroll
            for (int mt = 0; mt < 2; mt++)
#pragma unroll
                for (int nt = 0; nt < 8; nt++) {
                    float* c = acc[mt][nt];
                    asm volatile(
                        "mma.sync.aligned.m16n8k16.row.col.f32.f16.f16.f32 "
                        "{%0,%1,%2,%3},{%4,%5,%6,%7},{%8,%9},{%0,%1,%2,%3};"
                        : "+f"(c[0]), "+f"(c[1]), "+f"(c[2]), "+f"(c[3])
                        : "r"(afb[cb][mt][0]), "r"(afb[cb][mt][1]),
                          "r"(afb[cb][mt][2]), "r"(afb[cb][mt][3]),
                          "r"(bfb[cb][nt][0]), "r"(bfb[cb][nt][1]));
                }
        }
        if (++sidx == NSTAGE) sidx = 0;
    }
    __syncthreads();

    int ar = lane >> 2, ac = lane & 3;
    __half* hs = (__half*)smem;
#pragma unroll
    for (int mt = 0; mt < 2; mt++)
#pragma unroll
        for (int nt = 0; nt < 8; nt++) {
            int r = wm + mt * 16 + ar;
            int c = wn + nt * 8 + ac * 2;
            float* a = acc[mt][nt];
            *(__half2*)&hs[r * SLD + c]       = __floats2half2_rn(a[0], a[1]);
            *(__half2*)&hs[(r + 8) * SLD + c] = __floats2half2_rn(a[2], a[3]);
            float mx01 = fmaxf(a[0], a[2]);
            float mx11 = fmaxf(a[1], a[3]);
            atomicMax(&cms[c],     fenc(mx01));
            atomicMax(&cms[c + 1], fenc(mx11));
        }
    __syncthreads();

    __half* Sb = g_S + SBASE + (size_t)b * P * P;
    int ch = tid & 15;
    int r0 = tid >> 4;
#pragma unroll
    for (int i = 0; i < 8; i++) {
        int row = r0 + i * 16;
        uint4 v = *(uint4*)&hs[row * SLD + ch * 8];
        *(uint4*)&Sb[(size_t)(m0 + row) * P + n0 + ch * 8] = v;
    }
    if (tid < 128) atomicMax(&g_colmax[VB + b * P + n0 + tid], cms[tid]);
}

// ---- stage 5: colsum (L3: 8 cols/thread via uint4; L4 unchanged) ------------
__global__ void colsum_kernel() {
    int bid = blockIdx.x;
    if (bid < 1024) {
        int cb = bid & 1, yy = (bid >> 1) & 127, b = bid >> 8;
        int col = cb * 2048 + threadIdx.x * 8;
        int r0 = yy * 32;
        const unsigned* cm = g_colmax + b * P3 + col;
        float s1[8], s2[8];
#pragma unroll
        for (int j = 0; j < 8; j++) {
            float M = fdec(cm[j]);
            s1[j] = 2.0f / (1.0f - M + 2e-5f);
            s2[j] = M * s1[j];
        }
        const __half* Sb = g_S + (size_t)b * P3 * P3;
        float a[8] = {0,0,0,0,0,0,0,0};
#pragma unroll 4
        for (int r = r0; r < r0 + 32; r++) {
            uint4 u = *(const uint4*)&Sb[(size_t)r * P3 + col];
            float2 v0 = __half22float2(*(__half2*)&u.x);
            float2 v1 = __half22float2(*(__half2*)&u.y);
            float2 v2 = __half22float2(*(__half2*)&u.z);
            float2 v3 = __half22float2(*(__half2*)&u.w);
            a[0] += fast_exp(fmaf(v0.x, s1[0], -s2[0]));
            a[1] += fast_exp(fmaf(v0.y, s1[1], -s2[1]));
            a[2] += fast_exp(fmaf(v1.x, s1[2], -s2[2]));
            a[3] += fast_exp(fmaf(v1.y, s1[3], -s2[3]));
            a[4] += fast_exp(fmaf(v2.x, s1[4], -s2[4]));
            a[5] += fast_exp(fmaf(v2.y, s1[5], -s2[5]));
            a[6] += fast_exp(fmaf(v3.x, s1[6], -s2[6]));
            a[7] += fast_exp(fmaf(v3.y, s1[7], -s2[7]));
        }
        float* Zb = g_Z + b * P3 + col;
#pragma unroll
        for (int j = 0; j < 8; j++) atomicAdd(&Zb[j], a[j]);
    } else {
        int r = bid - 1024;
        int yy = r & 63, b = r >> 6;
        int col = threadIdx.x * 4;
        int r0 = yy * 16;
        int vb = V4_OFF + b * P4;
        const unsigned* cm = g_colmax + vb + col;
        float s1[4], s2[4];
#pragma unroll
        for (int j = 0; j < 4; j++) {
            float M = fdec(cm[j]);
            s1[j] = 2.0f / (1.0f - M + 2e-5f);
            s2[j] = M * s1[j];
        }
        const __half* Sb = g_S + S4_OFF + (size_t)b * P4 * P4;
        float a0 = 0.f, a1 = 0.f, a2 = 0.f, a3 = 0.f;
#pragma unroll 8
        for (int rr = r0; rr < r0 + 16; rr++) {
            uint2 u = *(const uint2*)&Sb[(size_t)rr * P4 + col];
            float2 v01 = __half22float2(*(__half2*)&u.x);
            float2 v23 = __half22float2(*(__half2*)&u.y);
            a0 += fast_exp(fmaf(v01.x, s1[0], -s2[0]));
            a1 += fast_exp(fmaf(v01.y, s1[1], -s2[1]));
            a2 += fast_exp(fmaf(v23.x, s1[2], -s2[2]));
            a3 += fast_exp(fmaf(v23.y, s1[3], -s2[3]));
        }
        float* Zb = g_Z + vb + col;
        atomicAdd(&Zb[0], a0);
        atomicAdd(&Zb[1], a1);
        atomicAdd(&Zb[2], a2);
        atomicAdd(&Zb[3], a3);
    }
}

// ---- stage 6: aux ------------------------------------------------------------
__global__ void aux_kernel() {
    int i = blockIdx.x * blockDim.x + threadIdx.x;
    if (i >= NVEC) return;
    float M = fdec(g_colmax[i]);
    float s1 = 2.0f / (1.0f - M + 2e-5f);
    g_s1[i] = s1;
    g_aux[i] = fmaf(M, s1, logf(g_Z[i]));
}

// ---- stage 7: rowmax + exp-sum, smem-cached s1/aux ---------------------------
__global__ void rowmax_kernel() {
    __shared__ float sh[8192];
    __shared__ float wsum[8];
    int bid = blockIdx.x;
    int rbase, P, vb, lidx;
    size_t sbase;
    if (bid < 512) {
        int b = bid >> 7, rb = bid & 127;
        rbase = rb * 32; P = P3;
        sbase = (size_t)b * P3 * P3; vb = b * P3; lidx = b;
    } else {
        int r = bid - 512;
        int b = r >> 5, rb = r & 31;
        rbase = rb * 32; P = P4;
        sbase = S4_OFF + (size_t)b * P4 * P4; vb = V4_OFF + b * P4; lidx = 4 + b;
    }
    int tid = threadIdx.x, lane = tid & 31, w = tid >> 5;
    for (int i = tid * 4; i < P; i += 1024) {
        *(float4*)&sh[i]     = *(const float4*)&g_s1[vb + i];
        *(float4*)&sh[P + i] = *(const float4*)&g_aux[vb + i];
    }
    __syncthreads();

    float es = 0.f;
#pragma unroll
    for (int rr = 0; rr < 4; rr++) {
        int row = rbase + w * 4 + rr;
        const __half* Sr = g_S + sbase + (size_t)row * P;
        float mx = -1e30f;
        for (int c = lane * 8; c < P; c += 256) {
            uint4 u = *(const uint4*)&Sr[c];
            float4 s0 = *(const float4*)&sh[c];
            float4 s1v = *(const float4*)&sh[c + 4];
            float4 a0 = *(const float4*)&sh[P + c];
            float4 a1 = *(const float4*)&sh[P + c + 4];
            float2 v0 = __half22float2(*(__half2*)&u.x);
            float2 v1 = __half22float2(*(__half2*)&u.y);
            float2 v2 = __half22float2(*(__half2*)&u.z);
            float2 v3 = __half22float2(*(__half2*)&u.w);
            mx = fmaxf(mx, fmaf(v0.x, s0.x, -a0.x));
            mx = fmaxf(mx, fmaf(v0.y, s0.y, -a0.y));
            mx = fmaxf(mx, fmaf(v1.x, s0.z, -a0.z));
            mx = fmaxf(mx, fmaf(v1.y, s0.w, -a0.w));
            mx = fmaxf(mx, fmaf(v2.x, s1v.x, -a1.x));
            mx = fmaxf(mx, fmaf(v2.y, s1v.y, -a1.y));
            mx = fmaxf(mx, fmaf(v3.x, s1v.z, -a1.z));
            mx = fmaxf(mx, fmaf(v3.y, s1v.w, -a1.w));
        }
#pragma unroll
        for (int o = 16; o; o >>= 1) mx = fmaxf(mx, __shfl_xor_sync(0xffffffffu, mx, o));
        es += fast_exp(mx);
    }
    if (lane == 0) wsum[w] = es;
    __syncthreads();
    if (tid == 0) {
        float s = 0.f;
#pragma unroll
        for (int i = 0; i < 8; i++) s += wsum[i];
        atomicAdd(&g_lsum[lidx], s);
    }
}

// ---- stage 8: final loss -------------------------------------------------------
__global__ void loss_final(float* out) {
    int i = threadIdx.x;
    float v = 0.f;
    if (i < 8) {
        float w = (i >> 2) ? 2.0f : 1.0f;
        float Pf = (i >> 2) ? (float)P4 : (float)P3;
        v = -w * logf(g_lsum[i] / Pf);
    }
#pragma unroll
    for (int o = 4; o; o >>= 1) v += __shfl_down_sync(0xffffffffu, v, o);
    if (i == 0) out[0] = v;
}

// ---------------------------------------------------------------------------
#define GEMM_SMEM (6 * ASTAGE)   // 104448 B

extern "C" void kernel_launch(void* const* d_in, const int* in_sizes, int n_in,
                              void* d_out, int out_size) {
    const float* g3 = (const float*)d_in[0];  // gen_relu3_2 [4,256,64,64]
    const float* t3 = (const float*)d_in[1];  // tar_relu3_2
    const float* g4 = (const float*)d_in[2];  // gen_relu4_2 [4,512,32,32]
    const float* t4 = (const float*)d_in[3];  // tar_relu4_2
    float* out = (float*)d_out;

    auto gemm3 = gemm_fp16_colmax<C3, P3, (size_t)0, (size_t)0, 0>;
    auto gemm4 = gemm_fp16_colmax<C4, P4, T4_OFF, S4_OFF, V4_OFF>;
    cudaFuncSetAttribute(gemm3, cudaFuncAttributeMaxDynamicSharedMemorySize, GEMM_SMEM);
    cudaFuncSetAttribute(gemm4, cudaFuncAttributeMaxDynamicSharedMemorySize, GEMM_SMEM);

    stats_kernel<<<768, 256>>>(g3, t3, g4, t4);
    finalize_kernel<<<(NVEC + 255) / 256, 256>>>(out);
    write_kernel<<<6144, 256>>>(g3, t3, g4, t4);
    gemm3<<<4096, 256, GEMM_SMEM>>>();
    gemm4<<<256, 256, GEMM_SMEM>>>();
    colsum_kernel<<<1280, 256>>>();
    aux_kernel<<<(NVEC + 255) / 256, 256>>>();
    rowmax_kernel<<<640, 256>>>();
    loss_final<<<1, 32>>>(out);
}

// round 16
// speedup vs baseline: 1.1125x; 1.1125x over previous
#include <cuda_runtime.h>
#include <cuda_fp16.h>
#include <cstdint>
#include <math.h>

// ---------------------------------------------------------------------------
// IDMRF loss. R12 configuration (best: 277us) + layer-4 chain overlapped on a
// second stream (graph-capturable fork/join via events).
//   Layer3: B=4, C=256, P=4096, w=1.  Layer4: B=4, C=512, P=1024, w=2.
// ---------------------------------------------------------------------------

#define P3 4096
#define C3 256
#define P4 1024
#define C4 512

#define S4_OFF  ((size_t)4 * P3 * P3)
#define T4_OFF  ((size_t)4 * C3 * P3)
#define V4_OFF  16384
#define NVEC    20480
#define PP4_OFF 524288

__device__ __half   g_S[S4_OFF + (size_t)4 * P4 * P4];
__device__ __half   g_tn[T4_OFF + (size_t)4 * C4 * P4];
__device__ __half   g_gn[T4_OFF + (size_t)4 * C4 * P4];
__device__ unsigned g_colmax[NVEC];
__device__ float    g_Z[NVEC];
__device__ float    g_s1[NVEC];
__device__ float    g_aux[NVEC];
__device__ float    g_lsum[8];
__device__ float    g_pst[PP4_OFF + 64 * 4096], g_pstt[PP4_OFF + 64 * 4096];
__device__ float    g_psg[PP4_OFF + 64 * 4096], g_psgg[PP4_OFF + 64 * 4096];
__device__ float    g_mean[NVEC], g_nt[NVEC], g_ng[NVEC];

__device__ __forceinline__ unsigned fenc(float f) {
    unsigned u = __float_as_uint(f);
    return (u & 0x80000000u) ? ~u : (u | 0x80000000u);
}
__device__ __forceinline__ float fdec(unsigned u) {
    return __uint_as_float((u & 0x80000000u) ? (u ^ 0x80000000u) : ~u);
}

__device__ __forceinline__ float fast_exp(float x) {
    float y = fmaxf(x * 1.4426950408889634f, -126.0f);
    float n = rintf(y);
    float f = y - n;
    float p = 1.3333558e-3f;
    p = fmaf(p, f, 9.6181291e-3f);
    p = fmaf(p, f, 5.5504109e-2f);
    p = fmaf(p, f, 2.4022651e-1f);
    p = fmaf(p, f, 6.9314718e-1f);
    p = fmaf(p, f, 1.0f);
    return p * __uint_as_float(((unsigned)((int)n + 127)) << 23);
}

__device__ __forceinline__ void ldsm4t(uint32_t& r0, uint32_t& r1,
                                       uint32_t& r2, uint32_t& r3, unsigned addr) {
    asm volatile("ldmatrix.sync.aligned.m8n8.x4.trans.shared.b16 {%0,%1,%2,%3},[%4];"
                 : "=r"(r0), "=r"(r1), "=r"(r2), "=r"(r3) : "r"(addr));
}

// ---- stage 1: split-K partial stats (both layers) ---------------------------
__global__ void stats_kernel(const float* __restrict__ gen3, const float* __restrict__ tar3,
                             const float* __restrict__ gen4, const float* __restrict__ tar4) {
    int bid = blockIdx.x;
    const float *g, *t;
    int P, sp, b, x, pbase, pstride;
    if (bid < 512) {
        x = bid & 3; sp = (bid >> 2) & 31; b = bid >> 7;
        g = gen3 + (size_t)b * C3 * P3; t = tar3 + (size_t)b * C3 * P3;
        P = P3; pbase = 0; pstride = 16384;
    } else {
        int r = bid - 512;
        x = 0; sp = r & 63; b = r >> 6;
        g = gen4 + (size_t)b * C4 * P4; t = tar4 + (size_t)b * C4 * P4;
        P = P4; pbase = PP4_OFF; pstride = 4096;
    }
    int hw = x * 1024 + threadIdx.x * 4;
    g += (size_t)(sp * 8) * P + hw;
    t += (size_t)(sp * 8) * P + hw;
    float st[4] = {0,0,0,0}, stt[4] = {0,0,0,0}, sg[4] = {0,0,0,0}, sgg[4] = {0,0,0,0};
#pragma unroll
    for (int c = 0; c < 8; c++) {
        float4 tv = *(const float4*)&t[(size_t)c * P];
        float4 gv = *(const float4*)&g[(size_t)c * P];
        st[0] += tv.x; stt[0] += tv.x * tv.x; sg[0] += gv.x; sgg[0] += gv.x * gv.x;
        st[1] += tv.y; stt[1] += tv.y * tv.y; sg[1] += gv.y; sgg[1] += gv.y * gv.y;
        st[2] += tv.z; stt[2] += tv.z * tv.z; sg[2] += gv.z; sgg[2] += gv.z * gv.z;
        st[3] += tv.w; stt[3] += tv.w * tv.w; sg[3] += gv.w; sgg[3] += gv.w * gv.w;
    }
    size_t base = (size_t)pbase + (size_t)sp * pstride + (size_t)b * P + hw;
    *(float4*)&g_pst[base]  = make_float4(st[0], st[1], st[2], st[3]);
    *(float4*)&g_pstt[base] = make_float4(stt[0], stt[1], stt[2], stt[3]);
    *(float4*)&g_psg[base]  = make_float4(sg[0], sg[1], sg[2], sg[3]);
    *(float4*)&g_psgg[base] = make_float4(sgg[0], sgg[1], sgg[2], sgg[3]);
}

// ---- stage 2: reduce partials; zero colmax/Z/lsum/out -----------------------
__global__ void finalize_kernel(float* out) {
    int i = blockIdx.x * blockDim.x + threadIdx.x;
    if (i >= NVEC) return;
    int C, NS, pbase, pstride, j;
    if (i < V4_OFF) { C = C3; NS = 32; pbase = 0; pstride = 16384; j = i; }
    else            { C = C4; NS = 64; pbase = PP4_OFF; pstride = 4096; j = i - V4_OFF; }
    float st = 0.f, stt = 0.f, sg = 0.f, sgg = 0.f;
    for (int s = 0; s < NS; s++) {
        size_t o = (size_t)pbase + (size_t)s * pstride + j;
        st += g_pst[o]; stt += g_pstt[o]; sg += g_psg[o]; sgg += g_psgg[o];
    }
    float mean = st / (float)C;
    float vt = stt - (float)C * mean * mean;
    float vg = sgg - 2.f * mean * sg + (float)C * mean * mean;
    g_mean[i] = mean;
    g_nt[i] = rsqrtf(fmaxf(vt, 1e-30f));
    g_ng[i] = rsqrtf(fmaxf(vg, 1e-30f));
    g_colmax[i] = 0u;
    g_Z[i] = 0.f;
    if (i < 8) g_lsum[i] = 0.f;
    if (i == 0) out[0] = 0.f;
}

// ---- stage 3: write normalized fp16 features (both layers) ------------------
__global__ void write_kernel(const float* __restrict__ gen3, const float* __restrict__ tar3,
                             const float* __restrict__ gen4, const float* __restrict__ tar4) {
    int bid = blockIdx.x;
    const float *g, *t;
    size_t foff, toff;
    int vb, c, hw, P;
    if (bid < 4096) {
        int b = bid >> 10, blk = bid & 1023;
        int idx = blk * 256 + threadIdx.x;
        c = idx >> 10; hw = (idx & 1023) * 4; P = P3;
        foff = (size_t)b * C3 * P3; toff = foff;
        g = gen3; t = tar3; vb = b * P3;
    } else {
        int r = bid - 4096;
        int b = r >> 9, blk = r & 511;
        int idx = blk * 256 + threadIdx.x;
        c = idx >> 8; hw = (idx & 255) * 4; P = P4;
        foff = (size_t)b * C4 * P4; toff = T4_OFF + foff;
        g = gen4; t = tar4; vb = V4_OFF + b * P4;
    }
    size_t off = foff + (size_t)c * P + hw;
    size_t dst = toff + (size_t)c * P + hw;
    size_t pb = (size_t)vb + hw;
    float4 tv = *(const float4*)&t[off];
    float4 gv = *(const float4*)&g[off];
    float4 mean = *(const float4*)&g_mean[pb];
    float4 nt   = *(const float4*)&g_nt[pb];
    float4 ng   = *(const float4*)&g_ng[pb];
    __half2 t01 = __floats2half2_rn((tv.x - mean.x) * nt.x, (tv.y - mean.y) * nt.y);
    __half2 t23 = __floats2half2_rn((tv.z - mean.z) * nt.z, (tv.w - mean.w) * nt.w);
    __half2 g01 = __floats2half2_rn((gv.x - mean.x) * ng.x, (gv.y - mean.y) * ng.y);
    __half2 g23 = __floats2half2_rn((gv.z - mean.z) * ng.z, (gv.w - mean.w) * ng.w);
    uint2 tp, gp;
    tp.x = *(unsigned*)&t01; tp.y = *(unsigned*)&t23;
    gp.x = *(unsigned*)&g01; gp.y = *(unsigned*)&g23;
    *(uint2*)&g_tn[dst] = tp;
    *(uint2*)&g_gn[dst] = gp;
}

// ---- stage 4: GEMM + colmax, templated; register fragment double-buffer -----
#define LDH 136
#define ASTAGE (64 * LDH * 2)
#define NSTAGE 3
#define SLD 136

template <int C, int P, size_t TBASE, size_t SBASE, int VB>
__global__ void __launch_bounds__(256, 2)
gemm_fp16_colmax() {
    extern __shared__ float smem[];
    __shared__ unsigned cms[128];
    constexpr int NTILE = P / 128;
    int bid = blockIdx.x;
    int b = bid / (NTILE * NTILE);
    int rem = bid % (NTILE * NTILE);
    int m0 = (rem / NTILE) * 128;
    int n0 = (rem % NTILE) * 128;
    const __half* Ab = g_tn + TBASE + (size_t)b * C * P;
    const __half* Bb = g_gn + TBASE + (size_t)b * C * P;
    int tid = threadIdx.x, lane = tid & 31, wid = tid >> 5;
    int wm = (wid & 3) * 32;
    int wn = (wid >> 2) * 64;
    if (tid < 128) cms[tid] = 0u;

    unsigned sA = (unsigned)__cvta_generic_to_shared(smem);
    unsigned sB = sA + (unsigned)NSTAGE * ASTAGE;

    float acc[2][8][4];
#pragma unroll
    for (int mt = 0; mt < 2; mt++)
#pragma unroll
        for (int nt = 0; nt < 8; nt++)
#pragma unroll
            for (int j = 0; j < 4; j++) acc[mt][nt][j] = 0.f;

    constexpr int nk = C / 64;

    auto issue_stage = [&](int s, int k0) {
#pragma unroll
        for (int i = 0; i < 4; i++) {
            int idx = tid + i * 256;
            int r = idx >> 4;
            int cm = (idx & 15) * 8;
            unsigned da = sA + (unsigned)s * ASTAGE + (unsigned)((r * LDH + cm) * 2);
            const __half* pa = Ab + (size_t)(k0 + r) * P + m0 + cm;
            asm volatile("cp.async.cg.shared.global [%0], [%1], 16;" :: "r"(da), "l"(pa));
            unsigned db = sB + (unsigned)s * ASTAGE + (unsigned)((r * LDH + cm) * 2);
            const __half* pb = Bb + (size_t)(k0 + r) * P + n0 + cm;
            asm volatile("cp.async.cg.shared.global [%0], [%1], 16;" :: "r"(db), "l"(pb));
        }
    };

    issue_stage(0, 0);
    asm volatile("cp.async.commit_group;");
    issue_stage(1, 64);
    asm volatile("cp.async.commit_group;");

    int g = lane >> 3, li = lane & 7;
    int akoff = (g >> 1) << 3, amoff = (g & 1) << 3;
    int bkoff = (g & 1) << 3,  bnoff = (g >> 1) << 3;

    uint32_t afb[2][2][4];
    uint32_t bfb[2][8][2];

    auto load_frags = [&](unsigned aS, unsigned bS, int kb, int buf) {
#pragma unroll
        for (int mt = 0; mt < 2; mt++) {
            int row = kb + akoff + li;
            int col = wm + mt * 16 + amoff;
            ldsm4t(afb[buf][mt][0], afb[buf][mt][1], afb[buf][mt][2], afb[buf][mt][3],
                   aS + (unsigned)((row * LDH + col) * 2));
        }
#pragma unroll
        for (int np = 0; np < 4; np++) {
            int row = kb + bkoff + li;
            int col = wn + np * 16 + bnoff;
            uint32_t r0, r1, r2, r3;
            ldsm4t(r0, r1, r2, r3, bS + (unsigned)((row * LDH + col) * 2));
            bfb[buf][np * 2][0] = r0; bfb[buf][np * 2][1] = r1;
            bfb[buf][np * 2 + 1][0] = r2; bfb[buf][np * 2 + 1][1] = r3;
        }
    };

    int sidx = 0;
    for (int kt = 0; kt < nk; kt++) {
        asm volatile("cp.async.wait_group 1;");
        __syncthreads();
        if (kt + 2 < nk) {
            int s2 = sidx + 2; if (s2 >= NSTAGE) s2 -= NSTAGE;
            issue_stage(s2, (kt + 2) * 64);
        }
        asm volatile("cp.async.commit_group;");
        unsigned aS = sA + (unsigned)sidx * ASTAGE;
        unsigned bS = sB + (unsigned)sidx * ASTAGE;
        load_frags(aS, bS, 0, 0);
#pragma unroll
        for (int k16 = 0; k16 < 4; k16++) {
            if (k16 < 3) load_frags(aS, bS, (k16 + 1) * 16, (k16 + 1) & 1);
            int cb = k16 & 1;
#pragma unroll
            for (int mt = 0; mt < 2; mt++)
#pragma unroll
                for (int nt = 0; nt < 8; nt++) {
                    float* c = acc[mt][nt];
                    asm volatile(
                        "mma.sync.aligned.m16n8k16.row.col.f32.f16.f16.f32 "
                        "{%0,%1,%2,%3},{%4,%5,%6,%7},{%8,%9},{%0,%1,%2,%3};"
                        : "+f"(c[0]), "+f"(c[1]), "+f"(c[2]), "+f"(c[3])
                        : "r"(afb[cb][mt][0]), "r"(afb[cb][mt][1]),
                          "r"(afb[cb][mt][2]), "r"(afb[cb][mt][3]),
                          "r"(bfb[cb][nt][0]), "r"(bfb[cb][nt][1]));
                }
        }
        if (++sidx == NSTAGE) sidx = 0;
    }
    __syncthreads();

    int ar = lane >> 2, ac = lane & 3;
    __half* hs = (__half*)smem;
#pragma unroll
    for (int mt = 0; mt < 2; mt++)
#pragma unroll
        for (int nt = 0; nt < 8; nt++) {
            int r = wm + mt * 16 + ar;
            int c = wn + nt * 8 + ac * 2;
            float* a = acc[mt][nt];
            *(__half2*)&hs[r * SLD + c]       = __floats2half2_rn(a[0], a[1]);
            *(__half2*)&hs[(r + 8) * SLD + c] = __floats2half2_rn(a[2], a[3]);
            float mx01 = fmaxf(a[0], a[2]);
            float mx11 = fmaxf(a[1], a[3]);
            atomicMax(&cms[c],     fenc(mx01));
            atomicMax(&cms[c + 1], fenc(mx11));
        }
    __syncthreads();

    __half* Sb = g_S + SBASE + (size_t)b * P * P;
    int ch = tid & 15;
    int r0 = tid >> 4;
#pragma unroll
    for (int i = 0; i < 8; i++) {
        int row = r0 + i * 16;
        uint4 v = *(uint4*)&hs[row * SLD + ch * 8];
        *(uint4*)&Sb[(size_t)(m0 + row) * P + n0 + ch * 8] = v;
    }
    if (tid < 128) atomicMax(&g_colmax[VB + b * P + n0 + tid], cms[tid]);
}

// ---- stage 5a: colsum layer3 (R12 shape: 4 cols/thread, 64 row-splits) ------
__global__ void colsum3_kernel() {
    int bid = blockIdx.x;
    int x = bid & 3, yy = (bid >> 2) & 63, b = bid >> 8;
    int col = (x * 256 + threadIdx.x) * 4;
    int r0 = yy * 64;
    const unsigned* cm = g_colmax + b * P3 + col;
    float s1[4], s2[4];
#pragma unroll
    for (int j = 0; j < 4; j++) {
        float M = fdec(cm[j]);
        s1[j] = 2.0f / (1.0f - M + 2e-5f);
        s2[j] = M * s1[j];
    }
    const __half* Sb = g_S + (size_t)b * P3 * P3;
    float a0 = 0.f, a1 = 0.f, a2 = 0.f, a3 = 0.f;
#pragma unroll 8
    for (int r = r0; r < r0 + 64; r++) {
        uint2 u = *(const uint2*)&Sb[(size_t)r * P3 + col];
        float2 v01 = __half22float2(*(__half2*)&u.x);
        float2 v23 = __half22float2(*(__half2*)&u.y);
        a0 += fast_exp(fmaf(v01.x, s1[0], -s2[0]));
        a1 += fast_exp(fmaf(v01.y, s1[1], -s2[1]));
        a2 += fast_exp(fmaf(v23.x, s1[2], -s2[2]));
        a3 += fast_exp(fmaf(v23.y, s1[3], -s2[3]));
    }
    float* Zb = g_Z + b * P3 + col;
    atomicAdd(&Zb[0], a0);
    atomicAdd(&Zb[1], a1);
    atomicAdd(&Zb[2], a2);
    atomicAdd(&Zb[3], a3);
}

// ---- stage 5b: colsum layer4 -------------------------------------------------
__global__ void colsum4_kernel() {
    int yy = blockIdx.x & 63, b = blockIdx.x >> 6;
    int col = threadIdx.x * 4;
    int r0 = yy * 16;
    int vb = V4_OFF + b * P4;
    const unsigned* cm = g_colmax + vb + col;
    float s1[4], s2[4];
#pragma unroll
    for (int j = 0; j < 4; j++) {
        float M = fdec(cm[j]);
        s1[j] = 2.0f / (1.0f - M + 2e-5f);
        s2[j] = M * s1[j];
    }
    const __half* Sb = g_S + S4_OFF + (size_t)b * P4 * P4;
    float a0 = 0.f, a1 = 0.f, a2 = 0.f, a3 = 0.f;
#pragma unroll 8
    for (int rr = r0; rr < r0 + 16; rr++) {
        uint2 u = *(const uint2*)&Sb[(size_t)rr * P4 + col];
        float2 v01 = __half22float2(*(__half2*)&u.x);
        float2 v23 = __half22float2(*(__half2*)&u.y);
        a0 += fast_exp(fmaf(v01.x, s1[0], -s2[0]));
        a1 += fast_exp(fmaf(v01.y, s1[1], -s2[1]));
        a2 += fast_exp(fmaf(v23.x, s1[2], -s2[2]));
        a3 += fast_exp(fmaf(v23.y, s1[3], -s2[3]));
    }
    float* Zb = g_Z + vb + col;
    atomicAdd(&Zb[0], a0);
    atomicAdd(&Zb[1], a1);
    atomicAdd(&Zb[2], a2);
    atomicAdd(&Zb[3], a3);
}

// ---- stage 6: aux (range-split) ------------------------------------------------
__global__ void aux_kernel(int base, int total) {
    int i = base + blockIdx.x * blockDim.x + threadIdx.x;
    if (i >= total) return;
    float M = fdec(g_colmax[i]);
    float s1 = 2.0f / (1.0f - M + 2e-5f);
    g_s1[i] = s1;
    g_aux[i] = fmaf(M, s1, logf(g_Z[i]));
}

// ---- stage 7: rowmax + exp-sum, smem-cached s1/aux (templated per layer) ------
template <int P, size_t SB, int VBASE, int LBASE>
__global__ void rowmax_kernel() {
    __shared__ float sh[8192];
    __shared__ float wsum[8];
    constexpr int RB = P / 32;      // row-blocks per batch
    int b = blockIdx.x / RB, rb = blockIdx.x % RB;
    int rbase = rb * 32;
    size_t sbase = SB + (size_t)b * P * P;
    int vb = VBASE + b * P;
    int lidx = LBASE + b;
    int tid = threadIdx.x, lane = tid & 31, w = tid >> 5;
    for (int i = tid * 4; i < P; i += 1024) {
        *(float4*)&sh[i]     = *(const float4*)&g_s1[vb + i];
        *(float4*)&sh[P + i] = *(const float4*)&g_aux[vb + i];
    }
    __syncthreads();

    float es = 0.f;
#pragma unroll
    for (int rr = 0; rr < 4; rr++) {
        int row = rbase + w * 4 + rr;
        const __half* Sr = g_S + sbase + (size_t)row * P;
        float mx = -1e30f;
        for (int c = lane * 8; c < P; c += 256) {
            uint4 u = *(const uint4*)&Sr[c];
            float4 s0 = *(const float4*)&sh[c];
            float4 s1v = *(const float4*)&sh[c + 4];
            float4 a0 = *(const float4*)&sh[P + c];
            float4 a1 = *(const float4*)&sh[P + c + 4];
            float2 v0 = __half22float2(*(__half2*)&u.x);
            float2 v1 = __half22float2(*(__half2*)&u.y);
            float2 v2 = __half22float2(*(__half2*)&u.z);
            float2 v3 = __half22float2(*(__half2*)&u.w);
            mx = fmaxf(mx, fmaf(v0.x, s0.x, -a0.x));
            mx = fmaxf(mx, fmaf(v0.y, s0.y, -a0.y));
            mx = fmaxf(mx, fmaf(v1.x, s0.z, -a0.z));
            mx = fmaxf(mx, fmaf(v1.y, s0.w, -a0.w));
            mx = fmaxf(mx, fmaf(v2.x, s1v.x, -a1.x));
            mx = fmaxf(mx, fmaf(v2.y, s1v.y, -a1.y));
            mx = fmaxf(mx, fmaf(v3.x, s1v.z, -a1.z));
            mx = fmaxf(mx, fmaf(v3.y, s1v.w, -a1.w));
        }
#pragma unroll
        for (int o = 16; o; o >>= 1) mx = fmaxf(mx, __shfl_xor_sync(0xffffffffu, mx, o));
        es += fast_exp(mx);
    }
    if (lane == 0) wsum[w] = es;
    __syncthreads();
    if (tid == 0) {
        float s = 0.f;
#pragma unroll
        for (int i = 0; i < 8; i++) s += wsum[i];
        atomicAdd(&g_lsum[lidx], s);
    }
}

// ---- stage 8: final loss -------------------------------------------------------
__global__ void loss_final(float* out) {
    int i = threadIdx.x;
    float v = 0.f;
    if (i < 8) {
        float w = (i >> 2) ? 2.0f : 1.0f;
        float Pf = (i >> 2) ? (float)P4 : (float)P3;
        v = -w * logf(g_lsum[i] / Pf);
    }
#pragma unroll
    for (int o = 4; o; o >>= 1) v += __shfl_down_sync(0xffffffffu, v, o);
    if (i == 0) out[0] = v;
}

// ---------------------------------------------------------------------------
#define GEMM_SMEM (6 * ASTAGE)   // 104448 B

extern "C" void kernel_launch(void* const* d_in, const int* in_sizes, int n_in,
                              void* d_out, int out_size) {
    const float* g3 = (const float*)d_in[0];  // gen_relu3_2 [4,256,64,64]
    const float* t3 = (const float*)d_in[1];  // tar_relu3_2
    const float* g4 = (const float*)d_in[2];  // gen_relu4_2 [4,512,32,32]
    const float* t4 = (const float*)d_in[3];  // tar_relu4_2
    float* out = (float*)d_out;

    // stream/event handles created once, on the first (uncaptured) call
    static cudaStream_t s2 = nullptr;
    static cudaEvent_t evFork = nullptr, evJoin = nullptr;
    if (s2 == nullptr) {
        cudaStreamCreateWithFlags(&s2, cudaStreamNonBlocking);
        cudaEventCreateWithFlags(&evFork, cudaEventDisableTiming);
        cudaEventCreateWithFlags(&evJoin, cudaEventDisableTiming);
    }

    auto gemm3 = gemm_fp16_colmax<C3, P3, (size_t)0, (size_t)0, 0>;
    auto gemm4 = gemm_fp16_colmax<C4, P4, T4_OFF, S4_OFF, V4_OFF>;
    cudaFuncSetAttribute(gemm3, cudaFuncAttributeMaxDynamicSharedMemorySize, GEMM_SMEM);
    cudaFuncSetAttribute(gemm4, cudaFuncAttributeMaxDynamicSharedMemorySize, GEMM_SMEM);

    // main stream: shared prologue
    stats_kernel<<<768, 256>>>(g3, t3, g4, t4);
    finalize_kernel<<<(NVEC + 255) / 256, 256>>>(out);
    write_kernel<<<6144, 256>>>(g3, t3, g4, t4);

    // fork: layer-4 chain on s2, overlapped with layer-3 GEMM
    cudaEventRecord(evFork, 0);
    cudaStreamWaitEvent(s2, evFork, 0);
    gemm4<<<256, 256, GEMM_SMEM, s2>>>();
    colsum4_kernel<<<256, 256, 0, s2>>>();
    aux_kernel<<<16, 256, 0, s2>>>(V4_OFF, NVEC);
    rowmax_kernel<P4, S4_OFF, V4_OFF, 4><<<128, 256, 0, s2>>>();
    cudaEventRecord(evJoin, s2);

    // main stream: layer-3 chain
    gemm3<<<4096, 256, GEMM_SMEM>>>();
    colsum3_kernel<<<1024, 256>>>();
    aux_kernel<<<64, 256>>>(0, V4_OFF);
    rowmax_kernel<P3, (size_t)0, 0, 0><<<512, 256>>>();

    // join + final reduction
    cudaStreamWaitEvent(0, evJoin, 0);
    loss_final<<<1, 32>>>(out);
}